// round 1
// baseline (speedup 1.0000x reference)
#include <cuda_runtime.h>
#include <cuda_bf16.h>
#include <math.h>

// Problem constants
#define BATCH   4
#define SEQ     4096
#define DMODEL  1024
#define DINNER  2048
#define DSTATE  16
#define MROWS   (BATCH*SEQ)          // 16384

// Scratch (device globals: allocation-free)
__device__ float g_xmain[MROWS*DINNER];   // 134 MB
__device__ float g_res[MROWS*DINNER];     // silu(res) stored directly
__device__ float g_xc[MROWS*DINNER];      // conv+silu output
__device__ float g_y[MROWS*DINNER];       // gated activations
__device__ float g_Bt[MROWS*DSTATE];
__device__ float g_Ct[MROWS*DSTATE];
__device__ float g_ys[MROWS];

__device__ __forceinline__ float siluf(float v) { return v / (1.0f + expf(-v)); }

// ---------------------------------------------------------------------------
// Tiled SGEMM: C[M,N] = A[M,K] * B[K,N], all row-major, M%128==0, N%128==0, K%16==0
// EPI==0: plain store to C0 (ld = N)
// EPI==1: split store — n < DINNER -> C0[m*DINNER+n]; else silu -> C1[m*DINNER+n-DINNER]
// ---------------------------------------------------------------------------
#define BM 128
#define BN 128
#define BK 16
#define TM 8
#define TN 8

template <int EPI>
__global__ __launch_bounds__(256)
void sgemm_kernel(int M, int N, int K,
                  const float* __restrict__ A, const float* __restrict__ Bm,
                  float* __restrict__ C0, float* __restrict__ C1)
{
    __shared__ float As[BK][BM];
    __shared__ float Bs[BK][BN];

    const int tid  = threadIdx.x;
    const int brow = blockIdx.y;
    const int bcol = blockIdx.x;

    const float* Ab = A + (size_t)brow * BM * K;
    const float* Bb = Bm + (size_t)bcol * BN;

    // A tile load mapping: 128 rows x 16 cols, float4
    const int arow = tid >> 2;           // 0..63
    const int acol = (tid & 3) * 4;      // 0,4,8,12
    // B tile load mapping: 16 rows x 128 cols, float4
    const int brw  = tid >> 5;           // 0..7
    const int bcl  = (tid & 31) * 4;

    const int trow = (tid >> 4) * TM;    // 0..120
    const int tcol = (tid & 15) * TN;

    float acc[TM][TN];
    #pragma unroll
    for (int i = 0; i < TM; i++)
        #pragma unroll
        for (int j = 0; j < TN; j++) acc[i][j] = 0.0f;

    for (int k0 = 0; k0 < K; k0 += BK) {
        #pragma unroll
        for (int o = 0; o < 2; o++) {
            float4 v = *(const float4*)(Ab + (size_t)(arow + o*64) * K + k0 + acol);
            As[acol+0][arow + o*64] = v.x;
            As[acol+1][arow + o*64] = v.y;
            As[acol+2][arow + o*64] = v.z;
            As[acol+3][arow + o*64] = v.w;
        }
        #pragma unroll
        for (int o = 0; o < 2; o++) {
            *(float4*)(&Bs[brw + o*8][bcl]) =
                *(const float4*)(Bb + (size_t)(k0 + brw + o*8) * N + bcl);
        }
        __syncthreads();

        #pragma unroll
        for (int k = 0; k < BK; k++) {
            float regM[TM], regN[TN];
            *(float4*)(&regM[0]) = *(const float4*)(&As[k][trow]);
            *(float4*)(&regM[4]) = *(const float4*)(&As[k][trow+4]);
            *(float4*)(&regN[0]) = *(const float4*)(&Bs[k][tcol]);
            *(float4*)(&regN[4]) = *(const float4*)(&Bs[k][tcol+4]);
            #pragma unroll
            for (int i = 0; i < TM; i++)
                #pragma unroll
                for (int j = 0; j < TN; j++)
                    acc[i][j] = fmaf(regM[i], regN[j], acc[i][j]);
        }
        __syncthreads();
    }

    const int crow0 = brow * BM + trow;
    const int ccol0 = bcol * BN + tcol;
    #pragma unroll
    for (int i = 0; i < TM; i++) {
        const int m = crow0 + i;
        #pragma unroll
        for (int j = 0; j < TN; j++) {
            const int n = ccol0 + j;
            float v = acc[i][j];
            if (EPI == 0) {
                C0[(size_t)m * N + n] = v;
            } else {
                if (n < DINNER) C0[(size_t)m * DINNER + n] = v;
                else            C1[(size_t)m * DINNER + (n - DINNER)] = siluf(v);
            }
        }
    }
}

// ---------------------------------------------------------------------------
// Depthwise conv3 along seq + bias + silu
// ---------------------------------------------------------------------------
__global__ __launch_bounds__(256)
void conv_silu_kernel(const float* __restrict__ xm, const float* __restrict__ cw,
                      const float* __restrict__ cb, float* __restrict__ xc)
{
    int idx = blockIdx.x * 256 + threadIdx.x;     // < MROWS*DINNER
    int i = idx & (DINNER - 1);
    int l = (idx >> 11) & (SEQ - 1);
    float w0 = cw[i*3], w1 = cw[i*3+1], w2 = cw[i*3+2];
    float v = cb[i] + w1 * xm[idx];
    if (l > 0)       v += w0 * xm[idx - DINNER];
    if (l < SEQ - 1) v += w2 * xm[idx + DINNER];
    xc[idx] = siluf(v);
}

// ---------------------------------------------------------------------------
// B/C projections: Bt[r,s] = sum_i xc[r,i] * W_B[i,s]; same for Ct.
// One block handles 16 rows; smem-tiled over i.
// ---------------------------------------------------------------------------
__global__ __launch_bounds__(256)
void bc_kernel(const float* __restrict__ xc, const float* __restrict__ WB,
               const float* __restrict__ WC, float* __restrict__ Bt,
               float* __restrict__ Ct)
{
    __shared__ float xs[16][129];
    __shared__ float wb[128][16];
    __shared__ float wc[128][16];

    const int row0 = blockIdx.x * 16;
    const int tid = threadIdx.x;
    const int r = tid >> 4, s = tid & 15;
    float accB = 0.0f, accC = 0.0f;

    for (int c0 = 0; c0 < DINNER; c0 += 128) {
        #pragma unroll
        for (int t = tid; t < 16*128; t += 256)
            xs[t >> 7][t & 127] = xc[(size_t)(row0 + (t >> 7)) * DINNER + c0 + (t & 127)];
        #pragma unroll
        for (int t = tid; t < 128*16; t += 256) {
            wb[t >> 4][t & 15] = WB[(size_t)(c0 + (t >> 4)) * DSTATE + (t & 15)];
            wc[t >> 4][t & 15] = WC[(size_t)(c0 + (t >> 4)) * DSTATE + (t & 15)];
        }
        __syncthreads();
        #pragma unroll 8
        for (int i = 0; i < 128; i++) {
            float xv = xs[r][i];
            accB = fmaf(xv, wb[i][s], accB);
            accC = fmaf(xv, wc[i][s], accC);
        }
        __syncthreads();
    }
    Bt[(size_t)(row0 + r) * DSTATE + s] = accB;
    Ct[(size_t)(row0 + r) * DSTATE + s] = accC;
}

// ---------------------------------------------------------------------------
// Sequential scan per batch. decay_s = sigmoid(-A_s). 16 lanes scan, smem-staged.
// ---------------------------------------------------------------------------
#define SCHUNK 256
__global__ __launch_bounds__(128)
void scan_kernel(const float* __restrict__ Bt, const float* __restrict__ Ct,
                 const float* __restrict__ A, float* __restrict__ ys)
{
    __shared__ float sb[SCHUNK * DSTATE];
    __shared__ float sc[SCHUNK * DSTATE];
    __shared__ float sy[SCHUNK];

    const int b = blockIdx.x;
    const int tid = threadIdx.x;
    const float* Bb = Bt + (size_t)b * SEQ * DSTATE;
    const float* Cb = Ct + (size_t)b * SEQ * DSTATE;

    float decay = 0.0f;
    if (tid < DSTATE) decay = 1.0f / (1.0f + expf(A[tid]));
    float st = 0.0f;

    for (int c = 0; c < SEQ / SCHUNK; c++) {
        for (int t = tid; t < SCHUNK * DSTATE; t += 128) {
            sb[t] = Bb[c * SCHUNK * DSTATE + t];
            sc[t] = Cb[c * SCHUNK * DSTATE + t];
        }
        __syncthreads();
        if (tid < DSTATE) {
            const int s = tid;
            #pragma unroll 4
            for (int t = 0; t < SCHUNK; t++) {
                st = fmaf(st, decay, sb[t * DSTATE + s]);
                float v = st * sc[t * DSTATE + s];
                #pragma unroll
                for (int o = 8; o > 0; o >>= 1)
                    v += __shfl_xor_sync(0xffffu, v, o, 16);
                if (s == 0) sy[t] = v;
            }
        }
        __syncthreads();
        for (int t = tid; t < SCHUNK; t += 128)
            ys[(size_t)b * SEQ + c * SCHUNK + t] = sy[t];
        __syncthreads();
    }
}

// ---------------------------------------------------------------------------
// Gating: y = (ys + xc * D) * silu_res
// ---------------------------------------------------------------------------
__global__ __launch_bounds__(256)
void gate_kernel(const float* __restrict__ xc, const float* __restrict__ resg,
                 const float* __restrict__ ys, const float* __restrict__ Dv,
                 float* __restrict__ y)
{
    int idx = blockIdx.x * 256 + threadIdx.x;
    int i = idx & (DINNER - 1);
    int row = idx >> 11;
    y[idx] = (ys[row] + xc[idx] * Dv[i]) * resg[idx];
}

// ---------------------------------------------------------------------------
extern "C" void kernel_launch(void* const* d_in, const int* in_sizes, int n_in,
                              void* d_out, int out_size)
{
    const float* x      = (const float*)d_in[0];
    const float* W_in   = (const float*)d_in[1];
    const float* conv_w = (const float*)d_in[2];
    const float* conv_b = (const float*)d_in[3];
    const float* W_B    = (const float*)d_in[4];
    const float* W_C    = (const float*)d_in[5];
    const float* A      = (const float*)d_in[6];
    const float* Dv     = (const float*)d_in[7];
    const float* W_out  = (const float*)d_in[8];
    float* out = (float*)d_out;

    float *xmain, *resg, *xc, *y, *Bt, *Ct, *ys;
    cudaGetSymbolAddress((void**)&xmain, g_xmain);
    cudaGetSymbolAddress((void**)&resg,  g_res);
    cudaGetSymbolAddress((void**)&xc,    g_xc);
    cudaGetSymbolAddress((void**)&y,     g_y);
    cudaGetSymbolAddress((void**)&Bt,    g_Bt);
    cudaGetSymbolAddress((void**)&Ct,    g_Ct);
    cudaGetSymbolAddress((void**)&ys,    g_ys);

    // 1) xr = x @ W_in, split into xmain / silu(res)
    {
        dim3 grid((2*DINNER) / BN, MROWS / BM);
        sgemm_kernel<1><<<grid, 256>>>(MROWS, 2*DINNER, DMODEL, x, W_in, xmain, resg);
    }
    // 2) depthwise conv + bias + silu
    conv_silu_kernel<<<(MROWS * DINNER) / 256, 256>>>(xmain, conv_w, conv_b, xc);
    // 3) B/C projections
    bc_kernel<<<MROWS / 16, 256>>>(xc, W_B, W_C, Bt, Ct);
    // 4) scan
    scan_kernel<<<BATCH, 128>>>(Bt, Ct, A, ys);
    // 5) gating
    gate_kernel<<<(MROWS * DINNER) / 256, 256>>>(xc, resg, ys, Dv, y);
    // 6) out = y @ W_out
    {
        dim3 grid(DMODEL / BN, MROWS / BM);
        sgemm_kernel<0><<<grid, 256>>>(MROWS, DMODEL, DINNER, y, W_out, out, nullptr);
    }
}

// round 2
// speedup vs baseline: 4.1567x; 4.1567x over previous
#include <cuda_runtime.h>
#include <cuda_bf16.h>
#include <math.h>

// Problem constants
#define BATCH   4
#define SEQ     4096
#define DMODEL  1024
#define DINNER  2048
#define DSTATE  16
#define MROWS   (BATCH*SEQ)          // 16384
#define NCHUNK  128
#define CLEN    32                   // SEQ / NCHUNK

// Scratch (device globals: allocation-free)
__device__ float g_xmain[MROWS*DINNER];
__device__ float g_res[MROWS*DINNER];     // silu(res) stored directly
__device__ float g_xc[MROWS*DINNER];
__device__ float g_y[MROWS*DINNER];
__device__ float g_Bt[MROWS*DSTATE];
__device__ float g_Ct[MROWS*DSTATE];
__device__ float g_ys[MROWS];
__device__ float g_carry[BATCH*NCHUNK*DSTATE];
__device__ float g_cin[BATCH*NCHUNK*DSTATE];

__device__ __forceinline__ float siluf(float v) { return v / (1.0f + expf(-v)); }
__device__ __forceinline__ float softplusf(float v) {
    return fmaxf(v, 0.0f) + log1pf(expf(-fabsf(v)));
}
__device__ __forceinline__ unsigned f2tf(float v) {
    unsigned r; asm("cvt.rna.tf32.f32 %0, %1;" : "=r"(r) : "f"(v)); return r;
}

// ---------------------------------------------------------------------------
// TF32 tensor-core GEMM: C[M,N] = A[M,K] * B[K,N], row-major.
// Block 128x128, BK=16, 8 warps in 2(m) x 4(n); warp tile 64x32.
// EPI==0: plain store. EPI==1: n<DINNER -> C0 ; else silu -> C1.
// ---------------------------------------------------------------------------
#define APAD 4
#define BPAD 8

template <int EPI>
__global__ __launch_bounds__(256)
void mma_gemm(int M, int N, int K,
              const float* __restrict__ A, const float* __restrict__ Bm,
              float* __restrict__ C0, float* __restrict__ C1)
{
    __shared__ unsigned As[128][16 + APAD];
    __shared__ unsigned Bs[16][128 + BPAD];

    const int tid  = threadIdx.x;
    const int wid  = tid >> 5;
    const int lane = tid & 31;
    const int wm   = wid >> 2;        // 0..1
    const int wn   = wid & 3;         // 0..3
    const int group = lane >> 2;      // 0..7
    const int tig   = lane & 3;       // 0..3

    const float* Ab = A + (size_t)blockIdx.y * 128 * K;
    const float* Bb = Bm + (size_t)blockIdx.x * 128;

    float acc[4][4][4];
    #pragma unroll
    for (int i = 0; i < 4; i++)
        #pragma unroll
        for (int j = 0; j < 4; j++)
            #pragma unroll
            for (int v = 0; v < 4; v++) acc[i][j][v] = 0.0f;

    for (int k0 = 0; k0 < K; k0 += 16) {
        // load A tile 128x16 (512 float4, 2 per thread)
        #pragma unroll
        for (int i = 0; i < 2; i++) {
            int id = tid + i * 256;
            int r = id >> 2, c = (id & 3) * 4;
            float4 v = *(const float4*)(Ab + (size_t)r * K + k0 + c);
            As[r][c+0] = f2tf(v.x); As[r][c+1] = f2tf(v.y);
            As[r][c+2] = f2tf(v.z); As[r][c+3] = f2tf(v.w);
        }
        // load B tile 16x128
        #pragma unroll
        for (int i = 0; i < 2; i++) {
            int id = tid + i * 256;
            int r = id >> 5, c = (id & 31) * 4;
            float4 v = *(const float4*)(Bb + (size_t)(k0 + r) * N + c);
            Bs[r][c+0] = f2tf(v.x); Bs[r][c+1] = f2tf(v.y);
            Bs[r][c+2] = f2tf(v.z); Bs[r][c+3] = f2tf(v.w);
        }
        __syncthreads();

        #pragma unroll
        for (int kk = 0; kk < 16; kk += 8) {
            unsigned afr[4][4], bfr[4][2];
            #pragma unroll
            for (int mt = 0; mt < 4; mt++) {
                int r0 = wm * 64 + mt * 16 + group;
                afr[mt][0] = As[r0    ][kk + tig];
                afr[mt][1] = As[r0 + 8][kk + tig];
                afr[mt][2] = As[r0    ][kk + tig + 4];
                afr[mt][3] = As[r0 + 8][kk + tig + 4];
            }
            #pragma unroll
            for (int nt = 0; nt < 4; nt++) {
                int c0 = wn * 32 + nt * 8 + group;
                bfr[nt][0] = Bs[kk + tig    ][c0];
                bfr[nt][1] = Bs[kk + tig + 4][c0];
            }
            #pragma unroll
            for (int mt = 0; mt < 4; mt++)
                #pragma unroll
                for (int nt = 0; nt < 4; nt++) {
                    asm volatile(
                        "mma.sync.aligned.m16n8k8.row.col.f32.tf32.tf32.f32 "
                        "{%0,%1,%2,%3}, {%4,%5,%6,%7}, {%8,%9}, {%0,%1,%2,%3};"
                        : "+f"(acc[mt][nt][0]), "+f"(acc[mt][nt][1]),
                          "+f"(acc[mt][nt][2]), "+f"(acc[mt][nt][3])
                        : "r"(afr[mt][0]), "r"(afr[mt][1]),
                          "r"(afr[mt][2]), "r"(afr[mt][3]),
                          "r"(bfr[nt][0]), "r"(bfr[nt][1]));
                }
        }
        __syncthreads();
    }

    const int crow = blockIdx.y * 128 + wm * 64;
    const int ccol = blockIdx.x * 128 + wn * 32;
    #pragma unroll
    for (int mt = 0; mt < 4; mt++) {
        #pragma unroll
        for (int nt = 0; nt < 4; nt++) {
            int r = crow + mt * 16 + group;
            int c = ccol + nt * 8 + tig * 2;
            float v0 = acc[mt][nt][0], v1 = acc[mt][nt][1];
            float v2 = acc[mt][nt][2], v3 = acc[mt][nt][3];
            if (EPI == 0) {
                *(float2*)(C0 + (size_t)r * N + c)       = make_float2(v0, v1);
                *(float2*)(C0 + (size_t)(r + 8) * N + c) = make_float2(v2, v3);
            } else {
                if (c < DINNER) {
                    *(float2*)(C0 + (size_t)r * DINNER + c)       = make_float2(v0, v1);
                    *(float2*)(C0 + (size_t)(r + 8) * DINNER + c) = make_float2(v2, v3);
                } else {
                    int cc = c - DINNER;
                    *(float2*)(C1 + (size_t)r * DINNER + cc)       = make_float2(siluf(v0), siluf(v1));
                    *(float2*)(C1 + (size_t)(r + 8) * DINNER + cc) = make_float2(siluf(v2), siluf(v3));
                }
            }
        }
    }
}

// ---------------------------------------------------------------------------
// Depthwise conv3 along seq + bias + silu (float4 over channel dim)
// ---------------------------------------------------------------------------
__global__ __launch_bounds__(256)
void conv_silu_kernel(const float4* __restrict__ xm, const float* __restrict__ cw,
                      const float* __restrict__ cb, float4* __restrict__ xc)
{
    int idx = blockIdx.x * 256 + threadIdx.x;       // float4 index
    int i4 = idx & (DINNER/4 - 1);
    int l  = (idx >> 9) & (SEQ - 1);
    float4 xmid = xm[idx];
    float4 xlo  = (l > 0)       ? xm[idx - DINNER/4] : make_float4(0,0,0,0);
    float4 xhi  = (l < SEQ - 1) ? xm[idx + DINNER/4] : make_float4(0,0,0,0);
    float4 out;
    #pragma unroll
    for (int j = 0; j < 4; j++) {
        int ch = i4 * 4 + j;
        float w0 = cw[ch*3], w1 = cw[ch*3+1], w2 = cw[ch*3+2];
        float a = (&xlo.x)[j], b = (&xmid.x)[j], cv = (&xhi.x)[j];
        float v = cb[ch] + w0 * a + w1 * b + w2 * cv;
        (&out.x)[j] = siluf(v);
    }
    xc[idx] = out;
}

// ---------------------------------------------------------------------------
// B/C projections
// ---------------------------------------------------------------------------
__global__ __launch_bounds__(256)
void bc_kernel(const float* __restrict__ xc, const float* __restrict__ WB,
               const float* __restrict__ WC, float* __restrict__ Bt,
               float* __restrict__ Ct)
{
    __shared__ float xs[16][129];
    __shared__ float wb[128][16];
    __shared__ float wc[128][16];

    const int row0 = blockIdx.x * 16;
    const int tid = threadIdx.x;
    const int r = tid >> 4, s = tid & 15;
    float accB = 0.0f, accC = 0.0f;

    for (int c0 = 0; c0 < DINNER; c0 += 128) {
        #pragma unroll
        for (int t = tid; t < 16*128; t += 256)
            xs[t >> 7][t & 127] = xc[(size_t)(row0 + (t >> 7)) * DINNER + c0 + (t & 127)];
        #pragma unroll
        for (int t = tid; t < 128*16; t += 256) {
            wb[t >> 4][t & 15] = WB[(size_t)(c0 + (t >> 4)) * DSTATE + (t & 15)];
            wc[t >> 4][t & 15] = WC[(size_t)(c0 + (t >> 4)) * DSTATE + (t & 15)];
        }
        __syncthreads();
        #pragma unroll 8
        for (int i = 0; i < 128; i++) {
            float xv = xs[r][i];
            accB = fmaf(xv, wb[i][s], accB);
            accC = fmaf(xv, wc[i][s], accC);
        }
        __syncthreads();
    }
    Bt[(size_t)(row0 + r) * DSTATE + s] = accB;
    Ct[(size_t)(row0 + r) * DSTATE + s] = accC;
}

// ---------------------------------------------------------------------------
// Parallel scan, stage A: per-(batch,chunk) local scan, zero initial state.
// Half-warp (16 lanes = 16 states) per chunk of 32 steps.
// ---------------------------------------------------------------------------
__global__ __launch_bounds__(256)
void scanA_kernel(const float* __restrict__ Bt, const float* __restrict__ Ct,
                  const float* __restrict__ A, float* __restrict__ ys,
                  float* __restrict__ carry)
{
    const int tid = threadIdx.x;
    const int w = blockIdx.x * 16 + (tid >> 4);   // half-warp id: 0..BATCH*NCHUNK-1
    const int s = tid & 15;
    const int b = w >> 7;            // NCHUNK=128 per batch
    const int ch = w & (NCHUNK - 1);

    const float d = 1.0f / (1.0f + expf(A[s]));   // exp(-softplus(A)) = sigmoid(-A)
    float st = 0.0f;

    const size_t base = ((size_t)b * SEQ + (size_t)ch * CLEN) * DSTATE + s;
    #pragma unroll 4
    for (int t = 0; t < CLEN; t++) {
        float bv = Bt[base + (size_t)t * DSTATE];
        float cv = Ct[base + (size_t)t * DSTATE];
        st = fmaf(st, d, bv);
        float v = st * cv;
        #pragma unroll
        for (int o = 8; o > 0; o >>= 1)
            v += __shfl_xor_sync(0xffffffffu, v, o, 16);
        if (s == 0) ys[(size_t)b * SEQ + ch * CLEN + t] = v;
    }
    carry[((size_t)b * NCHUNK + ch) * DSTATE + s] = st;
}

// ---------------------------------------------------------------------------
// Stage B: sequential carry combine. 64 threads = (b, s).
// cin[c] = state entering chunk c; cin[0]=0; cin[c] = carry[c-1] + d^CLEN * cin[c-1]
// ---------------------------------------------------------------------------
__global__ __launch_bounds__(64)
void scanB_kernel(const float* __restrict__ carry, const float* __restrict__ A,
                  float* __restrict__ cin)
{
    const int tid = threadIdx.x;
    const int b = tid >> 4, s = tid & 15;
    const float sp = softplusf(A[s]);
    const float dCL = expf(-sp * (float)CLEN);
    float in = 0.0f;
    for (int c = 0; c < NCHUNK; c++) {
        size_t off = ((size_t)b * NCHUNK + c) * DSTATE + s;
        cin[off] = in;
        in = fmaf(dCL, in, carry[off]);
    }
}

// ---------------------------------------------------------------------------
// Stage C: fixup. ys[row] += sum_s Ct[row,s] * d_s^{k+1} * cin[chunk,s]
// ---------------------------------------------------------------------------
__global__ __launch_bounds__(256)
void scanC_kernel(const float* __restrict__ Ct, const float* __restrict__ A,
                  const float* __restrict__ cin, float* __restrict__ ys)
{
    const int row = blockIdx.x * 256 + threadIdx.x;   // < MROWS
    const int b = row >> 12;
    const int t = row & (SEQ - 1);
    const int ch = t >> 5;          // CLEN=32
    const float kf = (float)((t & (CLEN - 1)) + 1);
    float sum = 0.0f;
    #pragma unroll
    for (int s = 0; s < DSTATE; s++) {
        float sp = softplusf(A[s]);
        float f = expf(-sp * kf);
        sum = fmaf(Ct[(size_t)row * DSTATE + s] * f,
                   cin[((size_t)b * NCHUNK + ch) * DSTATE + s], sum);
    }
    ys[row] += sum;
}

// ---------------------------------------------------------------------------
// Gating: y = (ys + xc * D) * silu_res  (float4)
// ---------------------------------------------------------------------------
__global__ __launch_bounds__(256)
void gate_kernel(const float4* __restrict__ xc, const float4* __restrict__ resg,
                 const float* __restrict__ ys, const float4* __restrict__ Dv,
                 float4* __restrict__ y)
{
    int idx = blockIdx.x * 256 + threadIdx.x;     // float4 index
    int i4 = idx & (DINNER/4 - 1);
    int row = idx >> 9;
    float yv = ys[row];
    float4 xcv = xc[idx], rg = resg[idx], dv = Dv[i4];
    float4 out;
    out.x = (yv + xcv.x * dv.x) * rg.x;
    out.y = (yv + xcv.y * dv.y) * rg.y;
    out.z = (yv + xcv.z * dv.z) * rg.z;
    out.w = (yv + xcv.w * dv.w) * rg.w;
    y[idx] = out;
}

// ---------------------------------------------------------------------------
extern "C" void kernel_launch(void* const* d_in, const int* in_sizes, int n_in,
                              void* d_out, int out_size)
{
    const float* x      = (const float*)d_in[0];
    const float* W_in   = (const float*)d_in[1];
    const float* conv_w = (const float*)d_in[2];
    const float* conv_b = (const float*)d_in[3];
    const float* W_B    = (const float*)d_in[4];
    const float* W_C    = (const float*)d_in[5];
    const float* A      = (const float*)d_in[6];
    const float* Dv     = (const float*)d_in[7];
    const float* W_out  = (const float*)d_in[8];
    float* out = (float*)d_out;

    float *xmain, *resg, *xc, *y, *Bt, *Ct, *ys, *carry, *cin;
    cudaGetSymbolAddress((void**)&xmain, g_xmain);
    cudaGetSymbolAddress((void**)&resg,  g_res);
    cudaGetSymbolAddress((void**)&xc,    g_xc);
    cudaGetSymbolAddress((void**)&y,     g_y);
    cudaGetSymbolAddress((void**)&Bt,    g_Bt);
    cudaGetSymbolAddress((void**)&Ct,    g_Ct);
    cudaGetSymbolAddress((void**)&ys,    g_ys);
    cudaGetSymbolAddress((void**)&carry, g_carry);
    cudaGetSymbolAddress((void**)&cin,   g_cin);

    // 1) xr = x @ W_in, split into xmain / silu(res)
    {
        dim3 grid((2*DINNER) / 128, MROWS / 128);
        mma_gemm<1><<<grid, 256>>>(MROWS, 2*DINNER, DMODEL, x, W_in, xmain, resg);
    }
    // 2) depthwise conv + bias + silu
    conv_silu_kernel<<<(MROWS * DINNER / 4) / 256, 256>>>(
        (const float4*)xmain, conv_w, conv_b, (float4*)xc);
    // 3) B/C projections
    bc_kernel<<<MROWS / 16, 256>>>(xc, W_B, W_C, Bt, Ct);
    // 4) scan (parallel 3-stage)
    scanA_kernel<<<(BATCH*NCHUNK) / 16, 256>>>(Bt, Ct, A, ys, carry);
    scanB_kernel<<<1, 64>>>(carry, A, cin);
    scanC_kernel<<<MROWS / 256, 256>>>(Ct, A, cin, ys);
    // 5) gating
    gate_kernel<<<(MROWS * DINNER / 4) / 256, 256>>>(
        (const float4*)xc, (const float4*)resg, ys, (const float4*)Dv, (float4*)y);
    // 6) out = y @ W_out
    {
        dim3 grid(DMODEL / 128, MROWS / 128);
        mma_gemm<0><<<grid, 256>>>(MROWS, DMODEL, DINNER, y, W_out, out, nullptr);
    }
}

// round 3
// speedup vs baseline: 5.0091x; 1.2051x over previous
#include <cuda_runtime.h>
#include <cuda_bf16.h>
#include <math.h>

// Problem constants
#define BATCH   4
#define SEQ     4096
#define DMODEL  1024
#define DINNER  2048
#define DSTATE  16
#define MROWS   (BATCH*SEQ)          // 16384
#define NCHUNK  128
#define CLEN    32                   // SEQ / NCHUNK

// Scratch (device globals: allocation-free)
__device__ float g_xmain[MROWS*DINNER];
__device__ float g_res[MROWS*DINNER];     // silu(res) stored directly
__device__ float g_xc[MROWS*DINNER];
__device__ float g_y[MROWS*DINNER];
__device__ float g_Bt[MROWS*DSTATE];
__device__ float g_Ct[MROWS*DSTATE];
__device__ float g_ys[MROWS];
__device__ float g_carry[BATCH*NCHUNK*DSTATE];
__device__ float g_cin[BATCH*NCHUNK*DSTATE];

__device__ __forceinline__ float siluf(float v) { return v / (1.0f + expf(-v)); }
__device__ __forceinline__ float softplusf(float v) {
    return fmaxf(v, 0.0f) + log1pf(expf(-fabsf(v)));
}
__device__ __forceinline__ unsigned f2tf(float v) {
    unsigned r; asm("cvt.rna.tf32.f32 %0, %1;" : "=r"(r) : "f"(v)); return r;
}
__device__ __forceinline__ void cpasync16(void* smem, const void* gmem) {
    unsigned s = (unsigned)__cvta_generic_to_shared(smem);
    asm volatile("cp.async.cg.shared.global [%0], [%1], 16;" :: "r"(s), "l"(gmem));
}

// ---------------------------------------------------------------------------
// TF32 tensor-core GEMM, cp.async double-buffered.
// C[M,N] = A[M,K] * B[K,N], row-major. Block 128x128, BK=32, 8 warps (2x4),
// warp tile 64x32. EPI==0: plain store. EPI==1: split + silu.
// smem layout (floats): As[2][128*36], Bs[2][32*136]
// ---------------------------------------------------------------------------
#define LDA 36
#define LDB 136
#define ASZ (128*LDA)
#define BSZ (32*LDB)
#define GEMM_SMEM ((2*(ASZ+BSZ))*4)

template <int EPI>
__global__ __launch_bounds__(256, 2)
void mma_gemm(int M, int N, int K,
              const float* __restrict__ A, const float* __restrict__ Bm,
              float* __restrict__ C0, float* __restrict__ C1)
{
    extern __shared__ float sm[];
    float* As = sm;               // [2][ASZ]
    float* Bs = sm + 2*ASZ;       // [2][BSZ]

    const int tid  = threadIdx.x;
    const int wid  = tid >> 5;
    const int lane = tid & 31;
    const int wm   = wid >> 2;        // 0..1
    const int wn   = wid & 3;         // 0..3
    const int group = lane >> 2;      // 0..7
    const int tig   = lane & 3;       // 0..3

    const float* Ab = A + (size_t)blockIdx.y * 128 * K;
    const float* Bb = Bm + (size_t)blockIdx.x * 128;

    float acc[4][4][4];
    #pragma unroll
    for (int i = 0; i < 4; i++)
        #pragma unroll
        for (int j = 0; j < 4; j++)
            #pragma unroll
            for (int v = 0; v < 4; v++) acc[i][j][v] = 0.0f;

    // async tile loaders: A tile 128x32 (8 float4/row), B tile 32x128 (32 float4/row)
    auto load_stage = [&](int st, int k0) {
        float* Ad = As + st * ASZ;
        float* Bd = Bs + st * BSZ;
        #pragma unroll
        for (int i = 0; i < 4; i++) {
            int id = tid + i * 256;
            int r = id >> 3, c4 = (id & 7) * 4;
            cpasync16(Ad + r * LDA + c4, Ab + (size_t)r * K + k0 + c4);
        }
        #pragma unroll
        for (int i = 0; i < 4; i++) {
            int id = tid + i * 256;
            int r = id >> 5, c4 = (id & 31) * 4;
            cpasync16(Bd + r * LDB + c4, Bb + (size_t)(k0 + r) * N + c4);
        }
        asm volatile("cp.async.commit_group;");
    };

    const int nk = K / 32;
    load_stage(0, 0);

    for (int kt = 0; kt < nk; kt++) {
        const int cur = kt & 1;
        if (kt + 1 < nk) {
            load_stage(cur ^ 1, (kt + 1) * 32);
            asm volatile("cp.async.wait_group 1;");
        } else {
            asm volatile("cp.async.wait_group 0;");
        }
        __syncthreads();

        const float* Ac = As + cur * ASZ;
        const float* Bc = Bs + cur * BSZ;
        #pragma unroll
        for (int kk = 0; kk < 32; kk += 8) {
            unsigned afr[4][4], bfr[4][2];
            #pragma unroll
            for (int mt = 0; mt < 4; mt++) {
                int r0 = wm * 64 + mt * 16 + group;
                afr[mt][0] = f2tf(Ac[r0 * LDA + kk + tig]);
                afr[mt][1] = f2tf(Ac[(r0 + 8) * LDA + kk + tig]);
                afr[mt][2] = f2tf(Ac[r0 * LDA + kk + tig + 4]);
                afr[mt][3] = f2tf(Ac[(r0 + 8) * LDA + kk + tig + 4]);
            }
            #pragma unroll
            for (int nt = 0; nt < 4; nt++) {
                int c0 = wn * 32 + nt * 8 + group;
                bfr[nt][0] = f2tf(Bc[(kk + tig) * LDB + c0]);
                bfr[nt][1] = f2tf(Bc[(kk + tig + 4) * LDB + c0]);
            }
            #pragma unroll
            for (int mt = 0; mt < 4; mt++)
                #pragma unroll
                for (int nt = 0; nt < 4; nt++) {
                    asm volatile(
                        "mma.sync.aligned.m16n8k8.row.col.f32.tf32.tf32.f32 "
                        "{%0,%1,%2,%3}, {%4,%5,%6,%7}, {%8,%9}, {%0,%1,%2,%3};"
                        : "+f"(acc[mt][nt][0]), "+f"(acc[mt][nt][1]),
                          "+f"(acc[mt][nt][2]), "+f"(acc[mt][nt][3])
                        : "r"(afr[mt][0]), "r"(afr[mt][1]),
                          "r"(afr[mt][2]), "r"(afr[mt][3]),
                          "r"(bfr[nt][0]), "r"(bfr[nt][1]));
                }
        }
        __syncthreads();
    }

    const int crow = blockIdx.y * 128 + wm * 64;
    const int ccol = blockIdx.x * 128 + wn * 32;
    #pragma unroll
    for (int mt = 0; mt < 4; mt++) {
        #pragma unroll
        for (int nt = 0; nt < 4; nt++) {
            int r = crow + mt * 16 + group;
            int c = ccol + nt * 8 + tig * 2;
            float v0 = acc[mt][nt][0], v1 = acc[mt][nt][1];
            float v2 = acc[mt][nt][2], v3 = acc[mt][nt][3];
            if (EPI == 0) {
                *(float2*)(C0 + (size_t)r * N + c)       = make_float2(v0, v1);
                *(float2*)(C0 + (size_t)(r + 8) * N + c) = make_float2(v2, v3);
            } else {
                if (c < DINNER) {
                    *(float2*)(C0 + (size_t)r * DINNER + c)       = make_float2(v0, v1);
                    *(float2*)(C0 + (size_t)(r + 8) * DINNER + c) = make_float2(v2, v3);
                } else {
                    int cc = c - DINNER;
                    *(float2*)(C1 + (size_t)r * DINNER + cc)       = make_float2(siluf(v0), siluf(v1));
                    *(float2*)(C1 + (size_t)(r + 8) * DINNER + cc) = make_float2(siluf(v2), siluf(v3));
                }
            }
        }
    }
}

// ---------------------------------------------------------------------------
// Depthwise conv3 along seq + bias + silu (float4 over channel dim)
// ---------------------------------------------------------------------------
__global__ __launch_bounds__(256)
void conv_silu_kernel(const float4* __restrict__ xm, const float* __restrict__ cw,
                      const float* __restrict__ cb, float4* __restrict__ xc)
{
    int idx = blockIdx.x * 256 + threadIdx.x;       // float4 index
    int i4 = idx & (DINNER/4 - 1);
    int l  = (idx >> 9) & (SEQ - 1);
    float4 xmid = xm[idx];
    float4 xlo  = (l > 0)       ? xm[idx - DINNER/4] : make_float4(0,0,0,0);
    float4 xhi  = (l < SEQ - 1) ? xm[idx + DINNER/4] : make_float4(0,0,0,0);
    float4 out;
    #pragma unroll
    for (int j = 0; j < 4; j++) {
        int ch = i4 * 4 + j;
        float w0 = cw[ch*3], w1 = cw[ch*3+1], w2 = cw[ch*3+2];
        float a = (&xlo.x)[j], b = (&xmid.x)[j], cv = (&xhi.x)[j];
        float v = cb[ch] + w0 * a + w1 * b + w2 * cv;
        (&out.x)[j] = siluf(v);
    }
    xc[idx] = out;
}

// ---------------------------------------------------------------------------
// B/C projections
// ---------------------------------------------------------------------------
__global__ __launch_bounds__(256)
void bc_kernel(const float* __restrict__ xc, const float* __restrict__ WB,
               const float* __restrict__ WC, float* __restrict__ Bt,
               float* __restrict__ Ct)
{
    __shared__ float xs[16][129];
    __shared__ float wb[128][16];
    __shared__ float wc[128][16];

    const int row0 = blockIdx.x * 16;
    const int tid = threadIdx.x;
    const int r = tid >> 4, s = tid & 15;
    float accB = 0.0f, accC = 0.0f;

    for (int c0 = 0; c0 < DINNER; c0 += 128) {
        #pragma unroll
        for (int t = tid; t < 16*128; t += 256)
            xs[t >> 7][t & 127] = xc[(size_t)(row0 + (t >> 7)) * DINNER + c0 + (t & 127)];
        #pragma unroll
        for (int t = tid; t < 128*16; t += 256) {
            wb[t >> 4][t & 15] = WB[(size_t)(c0 + (t >> 4)) * DSTATE + (t & 15)];
            wc[t >> 4][t & 15] = WC[(size_t)(c0 + (t >> 4)) * DSTATE + (t & 15)];
        }
        __syncthreads();
        #pragma unroll 8
        for (int i = 0; i < 128; i++) {
            float xv = xs[r][i];
            accB = fmaf(xv, wb[i][s], accB);
            accC = fmaf(xv, wc[i][s], accC);
        }
        __syncthreads();
    }
    Bt[(size_t)(row0 + r) * DSTATE + s] = accB;
    Ct[(size_t)(row0 + r) * DSTATE + s] = accC;
}

// ---------------------------------------------------------------------------
// Parallel scan, stage A: per-(batch,chunk) local scan, zero initial state.
// ---------------------------------------------------------------------------
__global__ __launch_bounds__(256)
void scanA_kernel(const float* __restrict__ Bt, const float* __restrict__ Ct,
                  const float* __restrict__ A, float* __restrict__ ys,
                  float* __restrict__ carry)
{
    const int tid = threadIdx.x;
    const int w = blockIdx.x * 16 + (tid >> 4);   // half-warp id
    const int s = tid & 15;
    const int b = w >> 7;
    const int ch = w & (NCHUNK - 1);

    const float d = 1.0f / (1.0f + expf(A[s]));
    float st = 0.0f;

    const size_t base = ((size_t)b * SEQ + (size_t)ch * CLEN) * DSTATE + s;
    #pragma unroll 4
    for (int t = 0; t < CLEN; t++) {
        float bv = Bt[base + (size_t)t * DSTATE];
        float cv = Ct[base + (size_t)t * DSTATE];
        st = fmaf(st, d, bv);
        float v = st * cv;
        #pragma unroll
        for (int o = 8; o > 0; o >>= 1)
            v += __shfl_xor_sync(0xffffffffu, v, o, 16);
        if (s == 0) ys[(size_t)b * SEQ + ch * CLEN + t] = v;
    }
    carry[((size_t)b * NCHUNK + ch) * DSTATE + s] = st;
}

// ---------------------------------------------------------------------------
// Stage B: sequential carry combine
// ---------------------------------------------------------------------------
__global__ __launch_bounds__(64)
void scanB_kernel(const float* __restrict__ carry, const float* __restrict__ A,
                  float* __restrict__ cin)
{
    const int tid = threadIdx.x;
    const int b = tid >> 4, s = tid & 15;
    const float sp = softplusf(A[s]);
    const float dCL = expf(-sp * (float)CLEN);
    float in = 0.0f;
    for (int c = 0; c < NCHUNK; c++) {
        size_t off = ((size_t)b * NCHUNK + c) * DSTATE + s;
        cin[off] = in;
        in = fmaf(dCL, in, carry[off]);
    }
}

// ---------------------------------------------------------------------------
// Stage C: fixup
// ---------------------------------------------------------------------------
__global__ __launch_bounds__(256)
void scanC_kernel(const float* __restrict__ Ct, const float* __restrict__ A,
                  const float* __restrict__ cin, float* __restrict__ ys)
{
    const int row = blockIdx.x * 256 + threadIdx.x;
    const int b = row >> 12;
    const int t = row & (SEQ - 1);
    const int ch = t >> 5;
    const float kf = (float)((t & (CLEN - 1)) + 1);
    float sum = 0.0f;
    #pragma unroll
    for (int s = 0; s < DSTATE; s++) {
        float sp = softplusf(A[s]);
        float f = expf(-sp * kf);
        sum = fmaf(Ct[(size_t)row * DSTATE + s] * f,
                   cin[((size_t)b * NCHUNK + ch) * DSTATE + s], sum);
    }
    ys[row] += sum;
}

// ---------------------------------------------------------------------------
// Gating: y = (ys + xc * D) * silu_res  (float4)
// ---------------------------------------------------------------------------
__global__ __launch_bounds__(256)
void gate_kernel(const float4* __restrict__ xc, const float4* __restrict__ resg,
                 const float* __restrict__ ys, const float4* __restrict__ Dv,
                 float4* __restrict__ y)
{
    int idx = blockIdx.x * 256 + threadIdx.x;
    int i4 = idx & (DINNER/4 - 1);
    int row = idx >> 9;
    float yv = ys[row];
    float4 xcv = xc[idx], rg = resg[idx], dv = Dv[i4];
    float4 out;
    out.x = (yv + xcv.x * dv.x) * rg.x;
    out.y = (yv + xcv.y * dv.y) * rg.y;
    out.z = (yv + xcv.z * dv.z) * rg.z;
    out.w = (yv + xcv.w * dv.w) * rg.w;
    y[idx] = out;
}

// ---------------------------------------------------------------------------
extern "C" void kernel_launch(void* const* d_in, const int* in_sizes, int n_in,
                              void* d_out, int out_size)
{
    const float* x      = (const float*)d_in[0];
    const float* W_in   = (const float*)d_in[1];
    const float* conv_w = (const float*)d_in[2];
    const float* conv_b = (const float*)d_in[3];
    const float* W_B    = (const float*)d_in[4];
    const float* W_C    = (const float*)d_in[5];
    const float* A      = (const float*)d_in[6];
    const float* Dv     = (const float*)d_in[7];
    const float* W_out  = (const float*)d_in[8];
    float* out = (float*)d_out;

    float *xmain, *resg, *xc, *y, *Bt, *Ct, *ys, *carry, *cin;
    cudaGetSymbolAddress((void**)&xmain, g_xmain);
    cudaGetSymbolAddress((void**)&resg,  g_res);
    cudaGetSymbolAddress((void**)&xc,    g_xc);
    cudaGetSymbolAddress((void**)&y,     g_y);
    cudaGetSymbolAddress((void**)&Bt,    g_Bt);
    cudaGetSymbolAddress((void**)&Ct,    g_Ct);
    cudaGetSymbolAddress((void**)&ys,    g_ys);
    cudaGetSymbolAddress((void**)&carry, g_carry);
    cudaGetSymbolAddress((void**)&cin,   g_cin);

    cudaFuncSetAttribute(mma_gemm<1>, cudaFuncAttributeMaxDynamicSharedMemorySize, GEMM_SMEM);
    cudaFuncSetAttribute(mma_gemm<0>, cudaFuncAttributeMaxDynamicSharedMemorySize, GEMM_SMEM);

    // 1) xr = x @ W_in, split into xmain / silu(res)
    {
        dim3 grid((2*DINNER) / 128, MROWS / 128);
        mma_gemm<1><<<grid, 256, GEMM_SMEM>>>(MROWS, 2*DINNER, DMODEL, x, W_in, xmain, resg);
    }
    // 2) depthwise conv + bias + silu
    conv_silu_kernel<<<(MROWS * DINNER / 4) / 256, 256>>>(
        (const float4*)xmain, conv_w, conv_b, (float4*)xc);
    // 3) B/C projections
    bc_kernel<<<MROWS / 16, 256>>>(xc, W_B, W_C, Bt, Ct);
    // 4) scan (parallel 3-stage)
    scanA_kernel<<<(BATCH*NCHUNK) / 16, 256>>>(Bt, Ct, A, ys, carry);
    scanB_kernel<<<1, 64>>>(carry, A, cin);
    scanC_kernel<<<MROWS / 256, 256>>>(Ct, A, cin, ys);
    // 5) gating
    gate_kernel<<<(MROWS * DINNER / 4) / 256, 256>>>(
        (const float4*)xc, (const float4*)resg, ys, (const float4*)Dv, (float4*)y);
    // 6) out = y @ W_out
    {
        dim3 grid(DMODEL / 128, MROWS / 128);
        mma_gemm<0><<<grid, 256, GEMM_SMEM>>>(MROWS, DMODEL, DINNER, y, W_out, out, nullptr);
    }
}